// round 1
// baseline (speedup 1.0000x reference)
#include <cuda_runtime.h>
#include <math.h>

// Shapes (fixed by setup_inputs)
#define B_  4
#define C_  64
#define H_  128
#define W_  128
#define HW  (H_*W_)          // 16384
#define OCF 576              // f_conv output channels = C*9
#define KTOT 576             // 64*9 reduction size

// Scratch (__device__ globals: allocation-free rule)
__device__ float g_psff[B_ * OCF * HW];   // 151 MB
__device__ float g_off[B_ * 18 * HW];
__device__ float g_m[B_ * 9 * HW];

// ---------------------------------------------------------------------------
// K1: small direct conv3x3 (OC = 18 or 9), optional sigmoid.
// One block per (b,h) row, 128 threads (one per w). IC chunked by 16.
// ---------------------------------------------------------------------------
template<int OC, int OCP, bool SIG>
__global__ void conv_small_kernel(const float* __restrict__ in,
                                  const float* __restrict__ wgt,
                                  const float* __restrict__ bias,
                                  float* __restrict__ out) {
    const int bh = blockIdx.x;
    const int b = bh >> 7;
    const int h = bh & 127;
    const int tid = threadIdx.x;      // 128 threads, tid == w
    const int w = tid;

    __shared__ __align__(16) float sIn[16 * 3 * 132];
    __shared__ __align__(16) float sW[144 * OCP];

    float acc[OCP];
#pragma unroll
    for (int i = 0; i < OCP; i++) acc[i] = 0.f;

    const float* inb = in + b * C_ * HW;

    for (int chunk = 0; chunk < 4; chunk++) {
        // zero-pad weight tile (pad columns read garbage otherwise)
        for (int idx = tid; idx < 144 * OCP; idx += 128) sW[idx] = 0.f;
        __syncthreads();
        // input tile: 16 ic x 3 rows x 130 cols
        for (int idx = tid; idx < 16 * 3 * 130; idx += 128) {
            int ic = idx / 390;
            int rem = idx - ic * 390;
            int r = rem / 130;
            int cc = rem - r * 130;
            int gh = h + r - 1;
            int gw = cc - 1;
            float v = 0.f;
            if ((unsigned)gh < 128u && (unsigned)gw < 128u)
                v = inb[(chunk * 16 + ic) * HW + gh * 128 + gw];
            sIn[(ic * 3 + r) * 132 + cc] = v;
        }
        // weight tile: [k=ic*9+s][oc]
        for (int idx = tid; idx < 144 * OC; idx += 128) {
            int oc = idx / 144;
            int k = idx - oc * 144;
            sW[k * OCP + oc] = wgt[oc * KTOT + chunk * 144 + k];
        }
        __syncthreads();

#pragma unroll 4
        for (int ic = 0; ic < 16; ic++) {
#pragma unroll
            for (int r = 0; r < 3; r++) {
                float v0 = sIn[(ic * 3 + r) * 132 + w];
                float v1 = sIn[(ic * 3 + r) * 132 + w + 1];
                float v2 = sIn[(ic * 3 + r) * 132 + w + 2];
#pragma unroll
                for (int dw = 0; dw < 3; dw++) {
                    float v = (dw == 0) ? v0 : ((dw == 1) ? v1 : v2);
                    const float4* wp = (const float4*)&sW[(ic * 9 + r * 3 + dw) * OCP];
#pragma unroll
                    for (int o4 = 0; o4 < OCP / 4; o4++) {
                        float4 wv = wp[o4];
                        acc[o4 * 4 + 0] += v * wv.x;
                        acc[o4 * 4 + 1] += v * wv.y;
                        acc[o4 * 4 + 2] += v * wv.z;
                        acc[o4 * 4 + 3] += v * wv.w;
                    }
                }
            }
        }
        __syncthreads();
    }

#pragma unroll
    for (int oc = 0; oc < OC; oc++) {
        float v = acc[oc] + bias[oc];
        if (SIG) v = 1.f / (1.f + expf(-v));
        out[((b * OC + oc) * 128 + h) * 128 + w] = v;
    }
}

// ---------------------------------------------------------------------------
// K2: big conv3x3 -> psff (576 output channels).
// Block: one (b,h) row (128 pixels) x 64 ocs. 256 threads.
// Thread tile: 8 pixels x 4 ocs. IC chunked by 8.
// ---------------------------------------------------------------------------
__global__ __launch_bounds__(256) void conv_big_kernel(
        const float* __restrict__ in,
        const float* __restrict__ wgt,
        const float* __restrict__ bias) {
    const int oc0 = blockIdx.x * 64;          // 0..8 tiles
    const int bh = blockIdx.y;
    const int b = bh >> 7;
    const int h = bh & 127;
    const int tid = threadIdx.x;
    const int tx = tid & 15;                  // pixel group (8 pixels)
    const int ty = tid >> 4;                  // oc group (4 ocs)
    const int wbase = tx * 8;

    __shared__ __align__(16) float sIn[8 * 3 * 132];
    __shared__ __align__(16) float sW[72 * 68];

    float acc[8][4];
#pragma unroll
    for (int p = 0; p < 8; p++)
#pragma unroll
        for (int j = 0; j < 4; j++) acc[p][j] = 0.f;

    const float* inb = in + b * C_ * HW;

    for (int chunk = 0; chunk < 8; chunk++) {
        // input: 8 ic x 3 rows x 130 cols
        for (int idx = tid; idx < 8 * 3 * 130; idx += 256) {
            int ic = idx / 390;
            int rem = idx - ic * 390;
            int r = rem / 130;
            int cc = rem - r * 130;
            int gh = h + r - 1;
            int gw = cc - 1;
            float v = 0.f;
            if ((unsigned)gh < 128u && (unsigned)gw < 128u)
                v = inb[(chunk * 8 + ic) * HW + gh * 128 + gw];
            sIn[(ic * 3 + r) * 132 + cc] = v;
        }
        // weights: 64 oc x 72 (ic*9+s), stored [k][oc] with row pad 68
        for (int idx = tid; idx < 64 * 72; idx += 256) {
            int oc = idx / 72;
            int k = idx - oc * 72;
            sW[k * 68 + oc] = wgt[(oc0 + oc) * KTOT + chunk * 72 + k];
        }
        __syncthreads();

#pragma unroll
        for (int ic = 0; ic < 8; ic++) {
#pragma unroll
            for (int r = 0; r < 3; r++) {
                const float* rowp = &sIn[(ic * 3 + r) * 132 + wbase];
                float4 t0 = *(const float4*)(rowp);
                float4 t1 = *(const float4*)(rowp + 4);
                float2 t2 = *(const float2*)(rowp + 8);
                float rw[10];
                rw[0] = t0.x; rw[1] = t0.y; rw[2] = t0.z; rw[3] = t0.w;
                rw[4] = t1.x; rw[5] = t1.y; rw[6] = t1.z; rw[7] = t1.w;
                rw[8] = t2.x; rw[9] = t2.y;
#pragma unroll
                for (int dw = 0; dw < 3; dw++) {
                    float4 wv = *(const float4*)&sW[(ic * 9 + r * 3 + dw) * 68 + ty * 4];
#pragma unroll
                    for (int p = 0; p < 8; p++) {
                        float a = rw[p + dw];
                        acc[p][0] += a * wv.x;
                        acc[p][1] += a * wv.y;
                        acc[p][2] += a * wv.z;
                        acc[p][3] += a * wv.w;
                    }
                }
            }
        }
        __syncthreads();
    }

    // epilogue: write 4 ocs x 8 pixels, vectorized
#pragma unroll
    for (int j = 0; j < 4; j++) {
        int oc = oc0 + ty * 4 + j;
        float bv = bias[oc];
        float4 o0 = make_float4(acc[0][j] + bv, acc[1][j] + bv, acc[2][j] + bv, acc[3][j] + bv);
        float4 o1 = make_float4(acc[4][j] + bv, acc[5][j] + bv, acc[6][j] + bv, acc[7][j] + bv);
        float* op = g_psff + (b * OCF + oc) * HW + h * 128 + wbase;
        *(float4*)op = o0;
        *(float4*)(op + 4) = o1;
    }
}

// ---------------------------------------------------------------------------
// K3: deformable sampling + modulation + 9-term reduce.
// out[b,c,h,w] = sum_t psff[b,c*9+t,h,w] * m[b,k',h',w'] * bilin(x[b,c], p)
// with (h',i') = (h-1,2) if i==0 else (h,i-1);  (w',j') analogous; t = 3i+j.
// One block per (b,h) row. Phase 1: per-(t,w) coefficient table in smem.
// Phase 2: c-loop gather/reduce.
// ---------------------------------------------------------------------------
__global__ __launch_bounds__(256) void epilogue_kernel(
        const float* __restrict__ x,
        float* __restrict__ out) {
    const int bh = blockIdx.x;
    const int b = bh >> 7;
    const int h = bh & 127;
    const int tid = threadIdx.x;

    __shared__ __align__(16) float sG[9 * 128 * 4];
    __shared__ __align__(16) int   sI[9 * 128 * 4];

    for (int item = tid; item < 9 * 128; item += 256) {
        int t = item >> 7;
        int w = item & 127;
        int i = t / 3, j = t - 3 * i;
        int hp = (i == 0) ? h - 1 : h;
        int ip = (i == 0) ? 2 : i - 1;
        int wp = (j == 0) ? w - 1 : w;
        int jp = (j == 0) ? 2 : j - 1;
        float g[4] = {0.f, 0.f, 0.f, 0.f};
        int id[4] = {-1, -1, -1, -1};
        if (hp >= 0 && wp >= 0) {
            int k = ip * 3 + jp;
            float dxk = (float)(ip - 1);
            float dyk = (float)(jp - 1);
            int obase = ((b * 18 + k) * 128 + hp) * 128 + wp;
            float ox = g_off[obase];
            float oy = g_off[obase + 9 * HW];
            float px = (float)(hp + 1) + dxk + ox;
            float py = (float)(wp + 1) + dyk + oy;
            float fx = floorf(px), fy = floorf(py);
            float ltx = fminf(fmaxf(fx, 0.f), 129.f);
            float lty = fminf(fmaxf(fy, 0.f), 129.f);
            float rbx = fminf(fmaxf(fx + 1.f, 0.f), 129.f);
            float rby = fminf(fmaxf(fy + 1.f, 0.f), 129.f);
            float pxc = fminf(fmaxf(px, 0.f), 129.f);
            float pyc = fminf(fmaxf(py, 0.f), 129.f);
            float gxl = 1.f + (ltx - pxc);
            float gxr = 1.f - (rbx - pxc);
            float gyl = 1.f + (lty - pyc);
            float gyr = 1.f - (rby - pyc);
            float mv = g_m[((b * 9 + k) * 128 + hp) * 128 + wp];
            int ax = (int)ltx - 1, ay = (int)lty - 1;
            int bx = (int)rbx - 1, by = (int)rby - 1;
            // lt, rb, lb, rt
            if ((unsigned)ax < 128u && (unsigned)ay < 128u) id[0] = ax * 128 + ay;
            if ((unsigned)bx < 128u && (unsigned)by < 128u) id[1] = bx * 128 + by;
            if ((unsigned)ax < 128u && (unsigned)by < 128u) id[2] = ax * 128 + by;
            if ((unsigned)bx < 128u && (unsigned)ay < 128u) id[3] = bx * 128 + ay;
            g[0] = gxl * gyl * mv;
            g[1] = gxr * gyr * mv;
            g[2] = gxl * gyr * mv;
            g[3] = gxr * gyl * mv;
        }
#pragma unroll
        for (int q = 0; q < 4; q++) {
            sG[(t * 128 + w) * 4 + q] = g[q];
            sI[(t * 128 + w) * 4 + q] = id[q];
        }
    }
    __syncthreads();

    const int w = tid & 127;
    const int c0 = tid >> 7;        // 0 or 1
    const int rowoff = h * 128 + w;
    const float* psb = g_psff + b * OCF * HW + rowoff;

    for (int cc = 0; cc < 32; cc++) {
        int c = cc * 2 + c0;
        const float* xpl = x + (b * C_ + c) * HW;
        float val = 0.f;
#pragma unroll
        for (int t = 0; t < 9; t++) {
            float s = 0.f;
#pragma unroll
            for (int q = 0; q < 4; q++) {
                int idx = sI[(t * 128 + w) * 4 + q];
                if (idx >= 0) s += sG[(t * 128 + w) * 4 + q] * __ldg(&xpl[idx]);
            }
            val += s * psb[(c * 9 + t) * HW];
        }
        out[(b * C_ + c) * HW + rowoff] = val;
    }
}

// ---------------------------------------------------------------------------
extern "C" void kernel_launch(void* const* d_in, const int* in_sizes, int n_in,
                              void* d_out, int out_size) {
    const float* feature_size    = (const float*)d_in[0];
    const float* feature_context = (const float*)d_in[1];
    const float* x               = (const float*)d_in[2];
    const float* p_conv_w        = (const float*)d_in[3];
    const float* p_conv_b        = (const float*)d_in[4];
    const float* f_conv_w        = (const float*)d_in[5];
    const float* f_conv_b        = (const float*)d_in[6];
    const float* m_conv_w        = (const float*)d_in[7];
    const float* m_conv_b        = (const float*)d_in[8];
    float* out = (float*)d_out;

    float* off_ptr; cudaGetSymbolAddress((void**)&off_ptr, g_off);
    float* m_ptr;   cudaGetSymbolAddress((void**)&m_ptr, g_m);

    // K1: offset conv (18 ch) and m conv (9 ch, sigmoid)
    conv_small_kernel<18, 20, false><<<B_ * H_, 128>>>(feature_size, p_conv_w, p_conv_b, off_ptr);
    conv_small_kernel<9, 12, true><<<B_ * H_, 128>>>(feature_size, m_conv_w, m_conv_b, m_ptr);

    // K2: psffilter conv (576 ch)
    dim3 grid2(OCF / 64, B_ * H_);
    conv_big_kernel<<<grid2, 256>>>(feature_context, f_conv_w, f_conv_b);

    // K3: sampling + modulate + reduce
    epilogue_kernel<<<B_ * H_, 256>>>(x, out);
}